// round 8
// baseline (speedup 1.0000x reference)
#include <cuda_runtime.h>
#include <cuda_bf16.h>
#include <cstdint>

#define NN 50000
#define EE 800000
#define FD 128           // hidden = heads*C = 2*64
#define NEG 0.2f
#define BN_EPS 1e-5f

// ---------------- scratch (device globals; referenced ONLY inside kernels) ----
__device__ __align__(16) float  g_h[NN * FD];    // per-layer features (GEMM out)
__device__ __align__(16) float  g_agg[NN * FD];  // GAT aggregate output (pre-BN)
__device__ float2 g_asrc[NN];
__device__ float2 g_adst[NN];
__device__ int    g_counts[NN];
__device__ int    g_cursor[NN];
__device__ int    g_offsets[NN + 1];
__device__ int    g_srt[EE];
__device__ double g_bnsum[2][FD];
__device__ double g_bnsq[2][FD];

__device__ __forceinline__ int clampN(int v) {
    return v < 0 ? 0 : (v >= NN ? NN - 1 : v);
}
__device__ __forceinline__ float lrelu(float v) { return v > 0.f ? v : NEG * v; }

__device__ __forceinline__ uint32_t f2tf32(float f) {
    uint32_t r;
    asm("cvt.rna.tf32.f32 %0, %1;" : "=r"(r) : "f"(f));
    return r;
}

#define MMA_TF32(d, a, b0, b1) \
    asm volatile("mma.sync.aligned.m16n8k8.row.col.f32.tf32.tf32.f32 " \
        "{%0,%1,%2,%3}, {%4,%5,%6,%7}, {%8,%9}, {%0,%1,%2,%3};" \
        : "+f"((d)[0]), "+f"((d)[1]), "+f"((d)[2]), "+f"((d)[3]) \
        : "r"((a)[0]), "r"((a)[1]), "r"((a)[2]), "r"((a)[3]), \
          "r"(b0), "r"(b1))

// ---------------- init / counting sort by destination -------------------------
__global__ void k_zero() {
    int i = blockIdx.x * blockDim.x + threadIdx.x;
    if (i < NN) g_counts[i] = 0;
    if (blockIdx.x == 0 && threadIdx.x < FD) {
        g_bnsum[0][threadIdx.x] = 0.0; g_bnsq[0][threadIdx.x] = 0.0;
        g_bnsum[1][threadIdx.x] = 0.0; g_bnsq[1][threadIdx.x] = 0.0;
    }
}

__global__ void k_hist(const int* __restrict__ dst) {
    int e4 = blockIdx.x * blockDim.x + threadIdx.x;
    if (e4 < EE / 4) {
        int4 d = ((const int4*)dst)[e4];
        atomicAdd(&g_counts[clampN(d.x)], 1);
        atomicAdd(&g_counts[clampN(d.y)], 1);
        atomicAdd(&g_counts[clampN(d.z)], 1);
        atomicAdd(&g_counts[clampN(d.w)], 1);
    }
}

__global__ void k_scan() {
    __shared__ int ssum[1024];
    const int CH = (NN + 1023) / 1024;
    int t = threadIdx.x;
    int base = t * CH;
    int s = 0;
    for (int i = 0; i < CH; i++) {
        int idx = base + i;
        if (idx < NN) s += g_counts[idx];
    }
    ssum[t] = s;
    __syncthreads();
    for (int o = 1; o < 1024; o <<= 1) {
        int u = (t >= o) ? ssum[t - o] : 0;
        __syncthreads();
        ssum[t] += u;
        __syncthreads();
    }
    int off = ssum[t] - s;
    for (int i = 0; i < CH; i++) {
        int idx = base + i;
        if (idx < NN) {
            g_offsets[idx] = off;
            g_cursor[idx]  = off;
            off += g_counts[idx];
        }
    }
    if (t == 0) g_offsets[NN] = EE;
}

__global__ void k_scatter(const int* __restrict__ src,
                          const int* __restrict__ dst) {
    int e4 = blockIdx.x * blockDim.x + threadIdx.x;
    if (e4 < EE / 4) {
        int4 d = ((const int4*)dst)[e4];
        int4 s = ((const int4*)src)[e4];
        int p;
        p = atomicAdd(&g_cursor[clampN(d.x)], 1); if (p >= 0 && p < EE) g_srt[p] = clampN(s.x);
        p = atomicAdd(&g_cursor[clampN(d.y)], 1); if (p >= 0 && p < EE) g_srt[p] = clampN(s.y);
        p = atomicAdd(&g_cursor[clampN(d.z)], 1); if (p >= 0 && p < EE) g_srt[p] = clampN(s.z);
        p = atomicAdd(&g_cursor[clampN(d.w)], 1); if (p >= 0 && p < EE) g_srt[p] = clampN(s.w);
    }
}

// ============== 3xTF32 mma.sync GEMM + attention-score epilogue ==============
// 256 threads = 8 warps. Block tile: 128 rows x 128 cols, K in 8 chunks of 16.
// Warp w owns rows [w*16, w*16+16). mma m16n8k8, 16 n-tiles, 3 products.
// A smem: [128][ASTR], tf32 bits, hi+lo.  B smem: [16][BSTR], tf32 bits, hi+lo.
#define ASTR 20    // row stride (floats); conflict-free A-fragment access
#define BSTR 136   // k-row stride; 136 % 32 == 8 -> conflict-free B access

__global__ void k_gemm_mma(const float* __restrict__ X, const float* __restrict__ W,
                           const float* __restrict__ gamma, const float* __restrict__ beta,
                           const float* __restrict__ att_s, const float* __restrict__ att_d,
                           int mode) {
    __shared__ uint32_t sAhi[128 * ASTR];
    __shared__ uint32_t sAlo[128 * ASTR];
    __shared__ uint32_t sBhi[16 * BSTR];
    __shared__ uint32_t sBlo[16 * BSTR];
    __shared__ float s_atts[FD], s_attd[FD], s_bnA[FD], s_bnB[FD];

    int t = threadIdx.x;
    int rb = blockIdx.x * 128;

    if (t < FD) {
        s_atts[t] = att_s[t];
        s_attd[t] = att_d[t];
        if (mode) {
            double mean = g_bnsum[0][t] / (double)NN;
            double var  = g_bnsq[0][t] / (double)NN - mean * mean;
            float a = gamma[t] * rsqrtf((float)var + BN_EPS);
            s_bnA[t] = a;
            s_bnB[t] = beta[t] - (float)mean * a;
        }
    }

    int lane = t & 31, warp = t >> 5;
    int g  = lane >> 2;       // groupID (row within fragment)
    int t4 = lane & 3;        // threadID in group
    int wr = warp * 16;       // warp row base within tile

    float d[16][4];
    #pragma unroll
    for (int nt = 0; nt < 16; nt++) {
        d[nt][0] = 0.f; d[nt][1] = 0.f; d[nt][2] = 0.f; d[nt][3] = 0.f;
    }

    const float4* X4 = (const float4*)(mode ? (const float*)g_agg : X);
    const float4* W4 = (const float4*)W;

    for (int kc = 0; kc < 8; kc++) {
        __syncthreads();   // includes: atts/bn ready (iter 0); prior compute done

        // --- stage A chunk: rows 0..127, k cols [kc*16, kc*16+16) ---
        #pragma unroll
        for (int j = 0; j < 2; j++) {
            int idx = t + j * 256;          // 512 float4 = 128 rows x 4 float4
            int row = idx >> 2, c4 = idx & 3;
            int grow = rb + row;
            float4 v = (grow < NN) ? X4[grow * 32 + kc * 4 + c4]
                                   : make_float4(0.f, 0.f, 0.f, 0.f);
            float vv[4] = {v.x, v.y, v.z, v.w};
            int sbase = row * ASTR + c4 * 4;
            #pragma unroll
            for (int i = 0; i < 4; i++) {
                float val = vv[i];
                if (mode) {
                    int c = kc * 16 + c4 * 4 + i;
                    float y = s_bnA[c] * val + s_bnB[c];
                    val = y > 0.f ? y : expm1f(y);
                }
                uint32_t hb = f2tf32(val);
                float lof = val - __uint_as_float(hb);
                sAhi[sbase + i] = hb;
                sAlo[sbase + i] = f2tf32(lof);
            }
        }

        // --- stage B chunk: W rows [kc*16, +16) x 128 n ---
        #pragma unroll
        for (int j = 0; j < 2; j++) {
            int idx = t + j * 256;          // 512 float4 = 16 k-rows x 32 float4
            int k = idx >> 5, c4 = idx & 31;
            float4 v = W4[(kc * 16 + k) * 32 + c4];
            float vv[4] = {v.x, v.y, v.z, v.w};
            int sbase = k * BSTR + c4 * 4;
            #pragma unroll
            for (int i = 0; i < 4; i++) {
                uint32_t hb = f2tf32(vv[i]);
                float lof = vv[i] - __uint_as_float(hb);
                sBhi[sbase + i] = hb;
                sBlo[sbase + i] = f2tf32(lof);
            }
        }
        __syncthreads();

        // --- compute: 2 k-steps of 8 ---
        #pragma unroll
        for (int ks = 0; ks < 2; ks++) {
            int kk = ks * 8;
            uint32_t ahi[4], alo[4];
            int ab = (wr + g) * ASTR + kk;
            ahi[0] = sAhi[ab + t4];
            ahi[1] = sAhi[ab + 8 * ASTR + t4];
            ahi[2] = sAhi[ab + t4 + 4];
            ahi[3] = sAhi[ab + 8 * ASTR + t4 + 4];
            alo[0] = sAlo[ab + t4];
            alo[1] = sAlo[ab + 8 * ASTR + t4];
            alo[2] = sAlo[ab + t4 + 4];
            alo[3] = sAlo[ab + 8 * ASTR + t4 + 4];
            #pragma unroll
            for (int nt = 0; nt < 16; nt++) {
                int bcol = nt * 8 + g;
                uint32_t bh0 = sBhi[(kk + t4) * BSTR + bcol];
                uint32_t bh1 = sBhi[(kk + t4 + 4) * BSTR + bcol];
                uint32_t bl0 = sBlo[(kk + t4) * BSTR + bcol];
                uint32_t bl1 = sBlo[(kk + t4 + 4) * BSTR + bcol];
                MMA_TF32(d[nt], ahi, bh0, bh1);
                MMA_TF32(d[nt], ahi, bl0, bl1);
                MMA_TF32(d[nt], alo, bh0, bh1);
            }
        }
    }

    // --- epilogue: store h, attention dots per head ---
    int r0 = rb + wr + g;
    int r1 = r0 + 8;
    float ds0h0 = 0.f, ds0h1 = 0.f, dd0h0 = 0.f, dd0h1 = 0.f;
    float ds1h0 = 0.f, ds1h1 = 0.f, dd1h0 = 0.f, dd1h1 = 0.f;
    #pragma unroll
    for (int nt = 0; nt < 16; nt++) {
        int c0 = nt * 8 + t4 * 2;
        float a0 = s_atts[c0], a1 = s_atts[c0 + 1];
        float b0 = s_attd[c0], b1 = s_attd[c0 + 1];
        float p0 = d[nt][0] * a0 + d[nt][1] * a1;
        float q0 = d[nt][0] * b0 + d[nt][1] * b1;
        float p1 = d[nt][2] * a0 + d[nt][3] * a1;
        float q1 = d[nt][2] * b0 + d[nt][3] * b1;
        if (nt < 8) { ds0h0 += p0; dd0h0 += q0; ds1h0 += p1; dd1h0 += q1; }
        else        { ds0h1 += p0; dd0h1 += q0; ds1h1 += p1; dd1h1 += q1; }
        if (r0 < NN) *(float2*)&g_h[r0 * FD + c0] = make_float2(d[nt][0], d[nt][1]);
        if (r1 < NN) *(float2*)&g_h[r1 * FD + c0] = make_float2(d[nt][2], d[nt][3]);
    }
    // reduce over the 4 lanes of each row group (t4 = 0..3)
    #pragma unroll
    for (int o = 1; o <= 2; o <<= 1) {
        ds0h0 += __shfl_xor_sync(0xFFFFFFFFu, ds0h0, o);
        ds0h1 += __shfl_xor_sync(0xFFFFFFFFu, ds0h1, o);
        dd0h0 += __shfl_xor_sync(0xFFFFFFFFu, dd0h0, o);
        dd0h1 += __shfl_xor_sync(0xFFFFFFFFu, dd0h1, o);
        ds1h0 += __shfl_xor_sync(0xFFFFFFFFu, ds1h0, o);
        ds1h1 += __shfl_xor_sync(0xFFFFFFFFu, ds1h1, o);
        dd1h0 += __shfl_xor_sync(0xFFFFFFFFu, dd1h0, o);
        dd1h1 += __shfl_xor_sync(0xFFFFFFFFu, dd1h1, o);
    }
    if (t4 == 0) {
        if (r0 < NN) {
            g_asrc[r0] = make_float2(ds0h0, ds0h1);
            g_adst[r0] = make_float2(dd0h0, dd0h1);
        }
        if (r1 < NN) {
            g_asrc[r1] = make_float2(ds1h0, ds1h1);
            g_adst[r1] = make_float2(dd1h0, dd1h1);
        }
    }
}

// ---------------- warp-per-dst aggregation (unchanged from R6) ----------------
__global__ void k_agg(const float* __restrict__ bias) {
    __shared__ int   s_src[8][32];
    __shared__ float s_a0[8][32];
    __shared__ float s_a1[8][32];
    int wb   = threadIdx.x >> 5;
    int lane = threadIdx.x & 31;
    int w = (blockIdx.x * blockDim.x + threadIdx.x) >> 5;
    if (w >= NN) return;
    int start = g_offsets[w];
    int deg   = g_offsets[w + 1] - start;

    float2 ad    = g_adst[w];
    float2 aself = g_asrc[w];

    bool have = lane < deg;
    int mysrc = 0;
    float2 ma = make_float2(-1e30f, -1e30f);
    if (have) { mysrc = g_srt[start + lane]; ma = g_asrc[mysrc]; }

    float M0 = fmaxf(ma.x, aself.x);
    float M1 = fmaxf(ma.y, aself.y);
    for (int j = 32 + lane; j < deg; j += 32) {
        float2 a = g_asrc[g_srt[start + j]];
        M0 = fmaxf(M0, a.x); M1 = fmaxf(M1, a.y);
    }
    #pragma unroll
    for (int o = 16; o; o >>= 1) {
        M0 = fmaxf(M0, __shfl_xor_sync(0xFFFFFFFFu, M0, o));
        M1 = fmaxf(M1, __shfl_xor_sync(0xFFFFFFFFu, M1, o));
    }
    float m0 = lrelu(M0 + ad.x);
    float m1 = lrelu(M1 + ad.y);

    float ex0 = 0.f, ex1 = 0.f;
    if (have) {
        ex0 = __expf(lrelu(ma.x + ad.x) - m0);
        ex1 = __expf(lrelu(ma.y + ad.y) - m1);
    }
    float s0 = ex0, s1 = ex1;
    for (int j = 32 + lane; j < deg; j += 32) {
        float2 a = g_asrc[g_srt[start + j]];
        s0 += __expf(lrelu(a.x + ad.x) - m0);
        s1 += __expf(lrelu(a.y + ad.y) - m1);
    }
    #pragma unroll
    for (int o = 16; o; o >>= 1) {
        s0 += __shfl_xor_sync(0xFFFFFFFFu, s0, o);
        s1 += __shfl_xor_sync(0xFFFFFFFFu, s1, o);
    }
    float xs0 = __expf(lrelu(aself.x + ad.x) - m0);
    float xs1 = __expf(lrelu(aself.y + ad.y) - m1);
    s0 += xs0; s1 += xs1;
    float inv0 = 1.f / (s0 + 1e-16f);
    float inv1 = 1.f / (s1 + 1e-16f);

    s_src[wb][lane] = mysrc;
    s_a0[wb][lane]  = ex0 * inv0;
    s_a1[wb][lane]  = ex1 * inv1;
    __syncwarp();

    int head = lane >> 4;
    const float4* H4 = (const float4*)g_h;

    float salpha = head ? xs1 * inv1 : xs0 * inv0;
    float4 hv = H4[w * 32 + lane];
    float4 acc = make_float4(salpha * hv.x, salpha * hv.y, salpha * hv.z, salpha * hv.w);

    const float* sal = head ? s_a1[wb] : s_a0[wb];
    int nd = deg < 32 ? deg : 32;
    #pragma unroll 4
    for (int j = 0; j < nd; j++) {
        int srcj = s_src[wb][j];
        float alpha = sal[j];
        float4 v = H4[srcj * 32 + lane];
        acc.x += alpha * v.x;
        acc.y += alpha * v.y;
        acc.z += alpha * v.z;
        acc.w += alpha * v.w;
    }
    for (int j = 32; j < deg; j++) {
        int srcj = g_srt[start + j];
        float2 a = g_asrc[srcj];
        float e = head ? (lrelu(a.y + ad.y) - m1) : (lrelu(a.x + ad.x) - m0);
        float alpha = __expf(e) * (head ? inv1 : inv0);
        float4 v = H4[srcj * 32 + lane];
        acc.x += alpha * v.x;
        acc.y += alpha * v.y;
        acc.z += alpha * v.z;
        acc.w += alpha * v.w;
    }

    float4 b = ((const float4*)bias)[lane];
    acc.x += b.x; acc.y += b.y; acc.z += b.z; acc.w += b.w;
    ((float4*)g_agg)[w * 32 + lane] = acc;
}

// ---------------- batch norm stats + final apply ------------------------------
__global__ void k_bnstats(int slot) {
    int c = threadIdx.x & 127;
    int g = threadIdx.x >> 7;
    float sum = 0.f, sq = 0.f;
    for (int r = blockIdx.x * 2 + g; r < NN; r += gridDim.x * 2) {
        float v = g_agg[r * FD + c];
        sum += v;
        sq = fmaf(v, v, sq);
    }
    atomicAdd(&g_bnsum[slot][c], (double)sum);
    atomicAdd(&g_bnsq[slot][c],  (double)sq);
}

__global__ void k_bnapply(const float* __restrict__ gamma,
                          const float* __restrict__ beta,
                          float* __restrict__ out) {
    int i = blockIdx.x * blockDim.x + threadIdx.x;
    if (i >= NN * 32) return;
    int c4 = (i & 31) * 4;
    float4 v  = ((const float4*)g_agg)[i];
    float4 gm = ((const float4*)gamma)[i & 31];
    float4 bt = ((const float4*)beta)[i & 31];
    float res[4];
    float vin[4] = {v.x, v.y, v.z, v.w};
    float gs[4]  = {gm.x, gm.y, gm.z, gm.w};
    float bs[4]  = {bt.x, bt.y, bt.z, bt.w};
    #pragma unroll
    for (int k = 0; k < 4; k++) {
        int c = c4 + k;
        float mean = (float)(g_bnsum[1][c] / (double)NN);
        float var  = (float)(g_bnsq[1][c] / (double)NN) - mean * mean;
        float is   = rsqrtf(var + BN_EPS);
        float y = (vin[k] - mean) * is * gs[k] + bs[k];
        res[k] = y > 0.f ? y : expm1f(y);
    }
    ((float4*)out)[i] = make_float4(res[0], res[1], res[2], res[3]);
}

// ---------------- launch: kernel launches ONLY (graph-capture safe) -----------
extern "C" void kernel_launch(void* const* d_in, const int* in_sizes, int n_in,
                              void* d_out, int out_size) {
    const float* x        = (const float*)d_in[0];
    const int*   eidx     = (const int*)d_in[1];
    const float* W1       = (const float*)d_in[2];
    const float* att_src1 = (const float*)d_in[3];
    const float* att_dst1 = (const float*)d_in[4];
    const float* b1       = (const float*)d_in[5];
    const float* W2       = (const float*)d_in[6];
    const float* att_src2 = (const float*)d_in[7];
    const float* att_dst2 = (const float*)d_in[8];
    const float* b2       = (const float*)d_in[9];
    const float* g1       = (const float*)d_in[10];
    const float* be1      = (const float*)d_in[11];
    const float* g2       = (const float*)d_in[12];
    const float* be2      = (const float*)d_in[13];
    float* out = (float*)d_out;

    const int* esrc = eidx;
    const int* edst = eidx + EE;

    const int WARP_BLOCKS = NN / 8;                 // 6250
    const int MMA_BLOCKS  = (NN + 127) / 128;       // 391
    const int E4_BLOCKS   = (EE / 4 + 255) / 256;

    k_zero<<<(NN + 255) / 256, 256>>>();
    k_hist<<<E4_BLOCKS, 256>>>(edst);
    k_scan<<<1, 1024>>>();
    k_scatter<<<E4_BLOCKS, 256>>>(esrc, edst);

    // --- layer 1 ---
    k_gemm_mma<<<MMA_BLOCKS, 256>>>(x, W1, g1, be1, att_src1, att_dst1, 0);
    k_agg<<<WARP_BLOCKS, 256>>>(b1);
    k_bnstats<<<256, 256>>>(0);

    // --- layer 2 (BN+ELU of layer 1 fused into A-load) ---
    k_gemm_mma<<<MMA_BLOCKS, 256>>>(x, W2, g1, be1, att_src2, att_dst2, 1);
    k_agg<<<WARP_BLOCKS, 256>>>(b2);
    k_bnstats<<<256, 256>>>(1);
    k_bnapply<<<WARP_BLOCKS, 256>>>(g2, be2, out);
}

// round 10
// speedup vs baseline: 1.0035x; 1.0035x over previous
#include <cuda_runtime.h>
#include <cuda_bf16.h>
#include <cstdint>

#define NN 50000
#define EE 800000
#define FD 128           // hidden = heads*C = 2*64
#define NEG 0.2f
#define BN_EPS 1e-5f

// ---------------- scratch (device globals; referenced ONLY inside kernels) ----
__device__ __align__(16) float  g_h[NN * FD];    // per-layer features (GEMM out)
__device__ __align__(16) float  g_agg[NN * FD];  // GAT aggregate output (pre-BN)
__device__ float2 g_asrc[NN];
__device__ float2 g_adst[NN];
__device__ int    g_counts[NN];
__device__ int    g_cursor[NN];
__device__ int    g_offsets[NN + 1];
__device__ int    g_srt[EE];
__device__ double g_bnsum[2][FD];
__device__ double g_bnsq[2][FD];
__device__ unsigned int g_gmax[2][2];   // [layer][head]: encoded global max of asrc

__device__ __forceinline__ int clampN(int v) {
    return v < 0 ? 0 : (v >= NN ? NN - 1 : v);
}
__device__ __forceinline__ float lrelu(float v) { return v > 0.f ? v : NEG * v; }

// monotone float<->uint encoding for atomicMax
__device__ __forceinline__ unsigned int encf(float f) {
    unsigned int u = __float_as_uint(f);
    return (u & 0x80000000u) ? ~u : (u | 0x80000000u);
}
__device__ __forceinline__ float decf(unsigned int u) {
    return __uint_as_float((u & 0x80000000u) ? (u ^ 0x80000000u) : ~u);
}

__device__ __forceinline__ uint32_t f2tf32(float f) {
    uint32_t r;
    asm("cvt.rna.tf32.f32 %0, %1;" : "=r"(r) : "f"(f));
    return r;
}

#define MMA_TF32(d, a, b0, b1) \
    asm volatile("mma.sync.aligned.m16n8k8.row.col.f32.tf32.tf32.f32 " \
        "{%0,%1,%2,%3}, {%4,%5,%6,%7}, {%8,%9}, {%0,%1,%2,%3};" \
        : "+f"((d)[0]), "+f"((d)[1]), "+f"((d)[2]), "+f"((d)[3]) \
        : "r"((a)[0]), "r"((a)[1]), "r"((a)[2]), "r"((a)[3]), \
          "r"(b0), "r"(b1))

// ---------------- init / counting sort by destination -------------------------
__global__ void k_zero() {
    int i = blockIdx.x * blockDim.x + threadIdx.x;
    if (i < NN) g_counts[i] = 0;
    if (blockIdx.x == 0 && threadIdx.x < FD) {
        g_bnsum[0][threadIdx.x] = 0.0; g_bnsq[0][threadIdx.x] = 0.0;
        g_bnsum[1][threadIdx.x] = 0.0; g_bnsq[1][threadIdx.x] = 0.0;
    }
    if (blockIdx.x == 0 && threadIdx.x < 4)
        g_gmax[threadIdx.x >> 1][threadIdx.x & 1] = 0u;
}

__global__ void k_hist(const int* __restrict__ dst) {
    int e4 = blockIdx.x * blockDim.x + threadIdx.x;
    if (e4 < EE / 4) {
        int4 d = ((const int4*)dst)[e4];
        atomicAdd(&g_counts[clampN(d.x)], 1);
        atomicAdd(&g_counts[clampN(d.y)], 1);
        atomicAdd(&g_counts[clampN(d.z)], 1);
        atomicAdd(&g_counts[clampN(d.w)], 1);
    }
}

__global__ void k_scan() {
    __shared__ int ssum[1024];
    const int CH = (NN + 1023) / 1024;
    int t = threadIdx.x;
    int base = t * CH;
    int s = 0;
    for (int i = 0; i < CH; i++) {
        int idx = base + i;
        if (idx < NN) s += g_counts[idx];
    }
    ssum[t] = s;
    __syncthreads();
    for (int o = 1; o < 1024; o <<= 1) {
        int u = (t >= o) ? ssum[t - o] : 0;
        __syncthreads();
        ssum[t] += u;
        __syncthreads();
    }
    int off = ssum[t] - s;
    for (int i = 0; i < CH; i++) {
        int idx = base + i;
        if (idx < NN) {
            g_offsets[idx] = off;
            g_cursor[idx]  = off;
            off += g_counts[idx];
        }
    }
    if (t == 0) g_offsets[NN] = EE;
}

__global__ void k_scatter(const int* __restrict__ src,
                          const int* __restrict__ dst) {
    int e4 = blockIdx.x * blockDim.x + threadIdx.x;
    if (e4 < EE / 4) {
        int4 d = ((const int4*)dst)[e4];
        int4 s = ((const int4*)src)[e4];
        int p;
        p = atomicAdd(&g_cursor[clampN(d.x)], 1); if (p >= 0 && p < EE) g_srt[p] = clampN(s.x);
        p = atomicAdd(&g_cursor[clampN(d.y)], 1); if (p >= 0 && p < EE) g_srt[p] = clampN(s.y);
        p = atomicAdd(&g_cursor[clampN(d.z)], 1); if (p >= 0 && p < EE) g_srt[p] = clampN(s.z);
        p = atomicAdd(&g_cursor[clampN(d.w)], 1); if (p >= 0 && p < EE) g_srt[p] = clampN(s.w);
    }
}

// ============== 3xTF32 mma.sync GEMM + attention-score epilogue ==============
#define ASTR 20    // A row stride (conflict-free fragment access)
#define BSTR 136   // B k-row stride; 136 % 32 == 8 -> conflict-free

__global__ void k_gemm_mma(const float* __restrict__ X, const float* __restrict__ W,
                           const float* __restrict__ gamma, const float* __restrict__ beta,
                           const float* __restrict__ att_s, const float* __restrict__ att_d,
                           int mode) {
    __shared__ uint32_t sAhi[128 * ASTR];
    __shared__ uint32_t sAlo[128 * ASTR];
    __shared__ uint32_t sBhi[16 * BSTR];
    __shared__ uint32_t sBlo[16 * BSTR];
    __shared__ float s_atts[FD], s_attd[FD], s_bnA[FD], s_bnB[FD];
    __shared__ unsigned int s_m0, s_m1;

    int t = threadIdx.x;
    int rb = blockIdx.x * 128;

    if (t == 0) { s_m0 = 0u; s_m1 = 0u; }
    if (t < FD) {
        s_atts[t] = att_s[t];
        s_attd[t] = att_d[t];
        if (mode) {
            double mean = g_bnsum[0][t] / (double)NN;
            double var  = g_bnsq[0][t] / (double)NN - mean * mean;
            float a = gamma[t] * rsqrtf((float)var + BN_EPS);
            s_bnA[t] = a;
            s_bnB[t] = beta[t] - (float)mean * a;
        }
    }

    int lane = t & 31, warp = t >> 5;
    int g  = lane >> 2;       // groupID (row within fragment)
    int t4 = lane & 3;        // threadID in group
    int wr = warp * 16;       // warp row base within tile

    float d[16][4];
    #pragma unroll
    for (int nt = 0; nt < 16; nt++) {
        d[nt][0] = 0.f; d[nt][1] = 0.f; d[nt][2] = 0.f; d[nt][3] = 0.f;
    }

    const float4* X4 = (const float4*)(mode ? (const float*)g_agg : X);
    const float4* W4 = (const float4*)W;

    for (int kc = 0; kc < 8; kc++) {
        __syncthreads();

        // --- stage A chunk ---
        #pragma unroll
        for (int j = 0; j < 2; j++) {
            int idx = t + j * 256;
            int row = idx >> 2, c4 = idx & 3;
            int grow = rb + row;
            float4 v = (grow < NN) ? X4[grow * 32 + kc * 4 + c4]
                                   : make_float4(0.f, 0.f, 0.f, 0.f);
            float vv[4] = {v.x, v.y, v.z, v.w};
            int sbase = row * ASTR + c4 * 4;
            #pragma unroll
            for (int i = 0; i < 4; i++) {
                float val = vv[i];
                if (mode) {
                    int c = kc * 16 + c4 * 4 + i;
                    float y = s_bnA[c] * val + s_bnB[c];
                    val = y > 0.f ? y : expm1f(y);
                }
                uint32_t hb = f2tf32(val);
                float lof = val - __uint_as_float(hb);
                sAhi[sbase + i] = hb;
                sAlo[sbase + i] = f2tf32(lof);
            }
        }

        // --- stage B chunk ---
        #pragma unroll
        for (int j = 0; j < 2; j++) {
            int idx = t + j * 256;
            int k = idx >> 5, c4 = idx & 31;
            float4 v = W4[(kc * 16 + k) * 32 + c4];
            float vv[4] = {v.x, v.y, v.z, v.w};
            int sbase = k * BSTR + c4 * 4;
            #pragma unroll
            for (int i = 0; i < 4; i++) {
                uint32_t hb = f2tf32(vv[i]);
                float lof = vv[i] - __uint_as_float(hb);
                sBhi[sbase + i] = hb;
                sBlo[sbase + i] = f2tf32(lof);
            }
        }
        __syncthreads();

        #pragma unroll
        for (int ks = 0; ks < 2; ks++) {
            int kk = ks * 8;
            uint32_t ahi[4], alo[4];
            int ab = (wr + g) * ASTR + kk;
            ahi[0] = sAhi[ab + t4];
            ahi[1] = sAhi[ab + 8 * ASTR + t4];
            ahi[2] = sAhi[ab + t4 + 4];
            ahi[3] = sAhi[ab + 8 * ASTR + t4 + 4];
            alo[0] = sAlo[ab + t4];
            alo[1] = sAlo[ab + 8 * ASTR + t4];
            alo[2] = sAlo[ab + t4 + 4];
            alo[3] = sAlo[ab + 8 * ASTR + t4 + 4];
            #pragma unroll
            for (int nt = 0; nt < 16; nt++) {
                int bcol = nt * 8 + g;
                uint32_t bh0 = sBhi[(kk + t4) * BSTR + bcol];
                uint32_t bh1 = sBhi[(kk + t4 + 4) * BSTR + bcol];
                uint32_t bl0 = sBlo[(kk + t4) * BSTR + bcol];
                uint32_t bl1 = sBlo[(kk + t4 + 4) * BSTR + bcol];
                MMA_TF32(d[nt], ahi, bh0, bh1);
                MMA_TF32(d[nt], ahi, bl0, bl1);
                MMA_TF32(d[nt], alo, bh0, bh1);
            }
        }
    }

    // --- epilogue: store h, attention dots per head, block max of asrc ---
    int r0 = rb + wr + g;
    int r1 = r0 + 8;
    float ds0h0 = 0.f, ds0h1 = 0.f, dd0h0 = 0.f, dd0h1 = 0.f;
    float ds1h0 = 0.f, ds1h1 = 0.f, dd1h0 = 0.f, dd1h1 = 0.f;
    #pragma unroll
    for (int nt = 0; nt < 16; nt++) {
        int c0 = nt * 8 + t4 * 2;
        float a0 = s_atts[c0], a1 = s_atts[c0 + 1];
        float b0 = s_attd[c0], b1 = s_attd[c0 + 1];
        float p0 = d[nt][0] * a0 + d[nt][1] * a1;
        float q0 = d[nt][0] * b0 + d[nt][1] * b1;
        float p1 = d[nt][2] * a0 + d[nt][3] * a1;
        float q1 = d[nt][2] * b0 + d[nt][3] * b1;
        if (nt < 8) { ds0h0 += p0; dd0h0 += q0; ds1h0 += p1; dd1h0 += q1; }
        else        { ds0h1 += p0; dd0h1 += q0; ds1h1 += p1; dd1h1 += q1; }
        if (r0 < NN) *(float2*)&g_h[r0 * FD + c0] = make_float2(d[nt][0], d[nt][1]);
        if (r1 < NN) *(float2*)&g_h[r1 * FD + c0] = make_float2(d[nt][2], d[nt][3]);
    }
    #pragma unroll
    for (int o = 1; o <= 2; o <<= 1) {
        ds0h0 += __shfl_xor_sync(0xFFFFFFFFu, ds0h0, o);
        ds0h1 += __shfl_xor_sync(0xFFFFFFFFu, ds0h1, o);
        dd0h0 += __shfl_xor_sync(0xFFFFFFFFu, dd0h0, o);
        dd0h1 += __shfl_xor_sync(0xFFFFFFFFu, dd0h1, o);
        ds1h0 += __shfl_xor_sync(0xFFFFFFFFu, ds1h0, o);
        ds1h1 += __shfl_xor_sync(0xFFFFFFFFu, ds1h1, o);
        dd1h0 += __shfl_xor_sync(0xFFFFFFFFu, dd1h0, o);
        dd1h1 += __shfl_xor_sync(0xFFFFFFFFu, dd1h1, o);
    }
    if (t4 == 0) {
        if (r0 < NN) {
            g_asrc[r0] = make_float2(ds0h0, ds0h1);
            g_adst[r0] = make_float2(dd0h0, dd0h1);
            atomicMax(&s_m0, encf(ds0h0));
            atomicMax(&s_m1, encf(ds0h1));
        }
        if (r1 < NN) {
            g_asrc[r1] = make_float2(ds1h0, ds1h1);
            g_adst[r1] = make_float2(dd1h0, dd1h1);
            atomicMax(&s_m0, encf(ds1h0));
            atomicMax(&s_m1, encf(ds1h1));
        }
    }
    __syncthreads();
    if (t == 0) {
        atomicMax(&g_gmax[mode][0], s_m0);
        atomicMax(&g_gmax[mode][1], s_m1);
    }
}

// ----- warp-per-dst aggregation: global-max softmax, single gather loop -------
__global__ void k_agg(const float* __restrict__ bias, int slot) {
    __shared__ int   s_src[8][64];
    __shared__ float s_a0[8][64];
    __shared__ float s_a1[8][64];
    int wb   = threadIdx.x >> 5;
    int lane = threadIdx.x & 31;
    int w = (blockIdx.x * blockDim.x + threadIdx.x) >> 5;
    if (w >= NN) return;
    int start = g_offsets[w];
    int deg   = g_offsets[w + 1] - start;

    float2 ad    = g_adst[w];
    float2 aself = g_asrc[w];
    float m0 = lrelu(decf(g_gmax[slot][0]) + ad.x);
    float m1 = lrelu(decf(g_gmax[slot][1]) + ad.y);

    // single pass: gather asrc, exp, stage (first 64 edges), accumulate sums
    float s0 = 0.f, s1 = 0.f;
    #pragma unroll
    for (int it = 0; it < 2; it++) {
        int j = it * 32 + lane;
        bool have = j < deg;
        int sj = 0;
        float x0 = 0.f, x1 = 0.f;
        if (have) {
            sj = g_srt[start + j];
            float2 a = g_asrc[sj];
            x0 = __expf(lrelu(a.x + ad.x) - m0);
            x1 = __expf(lrelu(a.y + ad.y) - m1);
        }
        s_src[wb][j < 64 ? j : lane] = sj;   // j always < 64 here
        s_a0[wb][it * 32 + lane] = x0;
        s_a1[wb][it * 32 + lane] = x1;
        s0 += x0; s1 += x1;
    }
    for (int j = 64 + lane; j < deg; j += 32) {   // astronomically rare tail
        float2 a = g_asrc[g_srt[start + j]];
        s0 += __expf(lrelu(a.x + ad.x) - m0);
        s1 += __expf(lrelu(a.y + ad.y) - m1);
    }
    #pragma unroll
    for (int o = 16; o; o >>= 1) {
        s0 += __shfl_xor_sync(0xFFFFFFFFu, s0, o);
        s1 += __shfl_xor_sync(0xFFFFFFFFu, s1, o);
    }
    float xs0 = __expf(lrelu(aself.x + ad.x) - m0);
    float xs1 = __expf(lrelu(aself.y + ad.y) - m1);
    s0 += xs0; s1 += xs1;
    float inv0 = 1.f / (s0 + 1e-16f);
    float inv1 = 1.f / (s1 + 1e-16f);

    // normalize own staged entries (lane-local), then make visible
    s_a0[wb][lane]      *= inv0;
    s_a0[wb][lane + 32] *= inv0;
    s_a1[wb][lane]      *= inv1;
    s_a1[wb][lane + 32] *= inv1;
    __syncwarp();

    int head = lane >> 4;
    const float4* H4 = (const float4*)g_h;

    float salpha = head ? xs1 * inv1 : xs0 * inv0;
    float4 hv = H4[w * 32 + lane];
    float4 acc = make_float4(salpha * hv.x, salpha * hv.y, salpha * hv.z, salpha * hv.w);

    const float* sal = head ? s_a1[wb] : s_a0[wb];
    int nd = deg < 64 ? deg : 64;
    #pragma unroll 4
    for (int j = 0; j < nd; j++) {
        int srcj = s_src[wb][j];
        float alpha = sal[j];
        float4 v = H4[srcj * 32 + lane];
        acc.x += alpha * v.x;
        acc.y += alpha * v.y;
        acc.z += alpha * v.z;
        acc.w += alpha * v.w;
    }
    for (int j = 64; j < deg; j++) {   // rare tail: recompute alpha inline
        int srcj = g_srt[start + j];
        float2 a = g_asrc[srcj];
        float e = head ? (lrelu(a.y + ad.y) - m1) : (lrelu(a.x + ad.x) - m0);
        float alpha = __expf(e) * (head ? inv1 : inv0);
        float4 v = H4[srcj * 32 + lane];
        acc.x += alpha * v.x;
        acc.y += alpha * v.y;
        acc.z += alpha * v.z;
        acc.w += alpha * v.w;
    }

    float4 b = ((const float4*)bias)[lane];
    acc.x += b.x; acc.y += b.y; acc.z += b.z; acc.w += b.w;
    ((float4*)g_agg)[w * 32 + lane] = acc;
}

// ---------------- batch norm stats + final apply ------------------------------
__global__ void k_bnstats(int slot) {
    int c = threadIdx.x & 127;
    int g = threadIdx.x >> 7;
    float sum = 0.f, sq = 0.f;
    for (int r = blockIdx.x * 2 + g; r < NN; r += gridDim.x * 2) {
        float v = g_agg[r * FD + c];
        sum += v;
        sq = fmaf(v, v, sq);
    }
    atomicAdd(&g_bnsum[slot][c], (double)sum);
    atomicAdd(&g_bnsq[slot][c],  (double)sq);
}

__global__ void k_bnapply(const float* __restrict__ gamma,
                          const float* __restrict__ beta,
                          float* __restrict__ out) {
    int i = blockIdx.x * blockDim.x + threadIdx.x;
    if (i >= NN * 32) return;
    int c4 = (i & 31) * 4;
    float4 v  = ((const float4*)g_agg)[i];
    float4 gm = ((const float4*)gamma)[i & 31];
    float4 bt = ((const float4*)beta)[i & 31];
    float res[4];
    float vin[4] = {v.x, v.y, v.z, v.w};
    float gs[4]  = {gm.x, gm.y, gm.z, gm.w};
    float bs[4]  = {bt.x, bt.y, bt.z, bt.w};
    #pragma unroll
    for (int k = 0; k < 4; k++) {
        int c = c4 + k;
        float mean = (float)(g_bnsum[1][c] / (double)NN);
        float var  = (float)(g_bnsq[1][c] / (double)NN) - mean * mean;
        float is   = rsqrtf(var + BN_EPS);
        float y = (vin[k] - mean) * is * gs[k] + bs[k];
        res[k] = y > 0.f ? y : expm1f(y);
    }
    ((float4*)out)[i] = make_float4(res[0], res[1], res[2], res[3]);
}

// ---------------- launch: kernel launches ONLY (graph-capture safe) -----------
extern "C" void kernel_launch(void* const* d_in, const int* in_sizes, int n_in,
                              void* d_out, int out_size) {
    const float* x        = (const float*)d_in[0];
    const int*   eidx     = (const int*)d_in[1];
    const float* W1       = (const float*)d_in[2];
    const float* att_src1 = (const float*)d_in[3];
    const float* att_dst1 = (const float*)d_in[4];
    const float* b1       = (const float*)d_in[5];
    const float* W2       = (const float*)d_in[6];
    const float* att_src2 = (const float*)d_in[7];
    const float* att_dst2 = (const float*)d_in[8];
    const float* b2       = (const float*)d_in[9];
    const float* g1       = (const float*)d_in[10];
    const float* be1      = (const float*)d_in[11];
    const float* g2       = (const float*)d_in[12];
    const float* be2      = (const float*)d_in[13];
    float* out = (float*)d_out;

    const int* esrc = eidx;
    const int* edst = eidx + EE;

    const int WARP_BLOCKS = NN / 8;                 // 6250
    const int MMA_BLOCKS  = (NN + 127) / 128;       // 391
    const int E4_BLOCKS   = (EE / 4 + 255) / 256;

    k_zero<<<(NN + 255) / 256, 256>>>();
    k_hist<<<E4_BLOCKS, 256>>>(edst);
    k_scan<<<1, 1024>>>();
    k_scatter<<<E4_BLOCKS, 256>>>(esrc, edst);

    // --- layer 1 ---
    k_gemm_mma<<<MMA_BLOCKS, 256>>>(x, W1, g1, be1, att_src1, att_dst1, 0);
    k_agg<<<WARP_BLOCKS, 256>>>(b1, 0);
    k_bnstats<<<256, 256>>>(0);

    // --- layer 2 (BN+ELU of layer 1 fused into A-load) ---
    k_gemm_mma<<<MMA_BLOCKS, 256>>>(x, W2, g1, be1, att_src2, att_dst2, 1);
    k_agg<<<WARP_BLOCKS, 256>>>(b2, 1);
    k_bnstats<<<256, 256>>>(1);
    k_bnapply<<<WARP_BLOCKS, 256>>>(g2, be2, out);
}

// round 11
// speedup vs baseline: 1.0437x; 1.0400x over previous
#include <cuda_runtime.h>
#include <cuda_bf16.h>
#include <cstdint>

#define NN 50000
#define EE 800000
#define FD 128           // hidden = heads*C = 2*64
#define NEG 0.2f
#define BN_EPS 1e-5f

// ---------------- scratch (device globals; referenced ONLY inside kernels) ----
__device__ __align__(16) float  g_h[NN * FD];    // per-layer features (GEMM out)
__device__ __align__(16) float  g_agg[NN * FD];  // GAT aggregate output (pre-BN)
__device__ __align__(16) uint32_t g_whi[2][FD * FD];  // W tf32-hi bits per layer
__device__ __align__(16) uint32_t g_wlo[2][FD * FD];  // W tf32-lo bits per layer
__device__ float2 g_asrc[NN];
__device__ float2 g_adst[NN];
__device__ int    g_counts[NN];
__device__ int    g_cursor[NN];
__device__ int    g_offsets[NN + 1];
__device__ int    g_srt[EE];
__device__ double g_bnsum[2][FD];
__device__ double g_bnsq[2][FD];
__device__ unsigned int g_gmax[2][2];   // [layer][head]: encoded global max of asrc

__device__ __forceinline__ int clampN(int v) {
    return v < 0 ? 0 : (v >= NN ? NN - 1 : v);
}
__device__ __forceinline__ float lrelu(float v) { return v > 0.f ? v : NEG * v; }

// monotone float<->uint encoding for atomicMax
__device__ __forceinline__ unsigned int encf(float f) {
    unsigned int u = __float_as_uint(f);
    return (u & 0x80000000u) ? ~u : (u | 0x80000000u);
}
__device__ __forceinline__ float decf(unsigned int u) {
    return __uint_as_float((u & 0x80000000u) ? (u ^ 0x80000000u) : ~u);
}

__device__ __forceinline__ uint32_t f2tf32(float f) {
    uint32_t r;
    asm("cvt.rna.tf32.f32 %0, %1;" : "=r"(r) : "f"(f));
    return r;
}

#define MMA_TF32(d, a, b0, b1) \
    asm volatile("mma.sync.aligned.m16n8k8.row.col.f32.tf32.tf32.f32 " \
        "{%0,%1,%2,%3}, {%4,%5,%6,%7}, {%8,%9}, {%0,%1,%2,%3};" \
        : "+f"((d)[0]), "+f"((d)[1]), "+f"((d)[2]), "+f"((d)[3]) \
        : "r"((a)[0]), "r"((a)[1]), "r"((a)[2]), "r"((a)[3]), \
          "r"(b0), "r"(b1))

// -------- prep: zero counters/stats + precompute W tf32 hi/lo (both layers) ---
__global__ void k_prep(const float* __restrict__ W1, const float* __restrict__ W2) {
    int i = blockIdx.x * blockDim.x + threadIdx.x;
    if (i < NN) g_counts[i] = 0;
    if (i < FD) {
        g_bnsum[0][i] = 0.0; g_bnsq[0][i] = 0.0;
        g_bnsum[1][i] = 0.0; g_bnsq[1][i] = 0.0;
    }
    if (i < 4) g_gmax[i >> 1][i & 1] = 0u;
    if (i < FD * FD) {
        #pragma unroll
        for (int l = 0; l < 2; l++) {
            float w = (l ? W2 : W1)[i];
            uint32_t hb = f2tf32(w);
            float lof = w - __uint_as_float(hb);
            g_whi[l][i] = hb;
            g_wlo[l][i] = f2tf32(lof);
        }
    }
}

// ---------------- counting sort by destination --------------------------------
__global__ void k_hist(const int* __restrict__ dst) {
    int e4 = blockIdx.x * blockDim.x + threadIdx.x;
    if (e4 < EE / 4) {
        int4 d = ((const int4*)dst)[e4];
        atomicAdd(&g_counts[clampN(d.x)], 1);
        atomicAdd(&g_counts[clampN(d.y)], 1);
        atomicAdd(&g_counts[clampN(d.z)], 1);
        atomicAdd(&g_counts[clampN(d.w)], 1);
    }
}

__global__ void k_scan() {
    __shared__ int ssum[1024];
    const int CH = (NN + 1023) / 1024;
    int t = threadIdx.x;
    int base = t * CH;
    int s = 0;
    for (int i = 0; i < CH; i++) {
        int idx = base + i;
        if (idx < NN) s += g_counts[idx];
    }
    ssum[t] = s;
    __syncthreads();
    for (int o = 1; o < 1024; o <<= 1) {
        int u = (t >= o) ? ssum[t - o] : 0;
        __syncthreads();
        ssum[t] += u;
        __syncthreads();
    }
    int off = ssum[t] - s;
    for (int i = 0; i < CH; i++) {
        int idx = base + i;
        if (idx < NN) {
            g_offsets[idx] = off;
            g_cursor[idx]  = off;
            off += g_counts[idx];
        }
    }
    if (t == 0) g_offsets[NN] = EE;
}

__global__ void k_scatter(const int* __restrict__ src,
                          const int* __restrict__ dst) {
    int e4 = blockIdx.x * blockDim.x + threadIdx.x;
    if (e4 < EE / 4) {
        int4 d = ((const int4*)dst)[e4];
        int4 s = ((const int4*)src)[e4];
        int p;
        p = atomicAdd(&g_cursor[clampN(d.x)], 1); if (p >= 0 && p < EE) g_srt[p] = clampN(s.x);
        p = atomicAdd(&g_cursor[clampN(d.y)], 1); if (p >= 0 && p < EE) g_srt[p] = clampN(s.y);
        p = atomicAdd(&g_cursor[clampN(d.z)], 1); if (p >= 0 && p < EE) g_srt[p] = clampN(s.z);
        p = atomicAdd(&g_cursor[clampN(d.w)], 1); if (p >= 0 && p < EE) g_srt[p] = clampN(s.w);
    }
}

// ============== 3xTF32 mma.sync GEMM + attention-score epilogue ==============
// A hi-split via mantissa mask (LOP3+FADD+LOP3, no cvt); B preconverted in k_prep.
#define ASTR 20    // A row stride (conflict-free fragment access)
#define BSTR 136   // B k-row stride; 136 % 32 == 8 -> conflict-free
#define TF32_MASK 0xFFFFE000u

__global__ void k_gemm_mma(const float* __restrict__ X,
                           const float* __restrict__ gamma, const float* __restrict__ beta,
                           const float* __restrict__ att_s, const float* __restrict__ att_d,
                           int mode) {
    __shared__ uint32_t sAhi[128 * ASTR];
    __shared__ uint32_t sAlo[128 * ASTR];
    __shared__ uint32_t sBhi[16 * BSTR];
    __shared__ uint32_t sBlo[16 * BSTR];
    __shared__ float s_atts[FD], s_attd[FD], s_bnA[FD], s_bnB[FD];
    __shared__ unsigned int s_m0, s_m1;

    int t = threadIdx.x;
    int rb = blockIdx.x * 128;

    if (t == 0) { s_m0 = 0u; s_m1 = 0u; }
    if (t < FD) {
        s_atts[t] = att_s[t];
        s_attd[t] = att_d[t];
        if (mode) {
            double mean = g_bnsum[0][t] / (double)NN;
            double var  = g_bnsq[0][t] / (double)NN - mean * mean;
            float a = gamma[t] * rsqrtf((float)var + BN_EPS);
            s_bnA[t] = a;
            s_bnB[t] = beta[t] - (float)mean * a;
        }
    }

    int lane = t & 31, warp = t >> 5;
    int g  = lane >> 2;       // groupID (row within fragment)
    int t4 = lane & 3;        // threadID in group
    int wr = warp * 16;       // warp row base within tile

    float d[16][4];
    #pragma unroll
    for (int nt = 0; nt < 16; nt++) {
        d[nt][0] = 0.f; d[nt][1] = 0.f; d[nt][2] = 0.f; d[nt][3] = 0.f;
    }

    const float4* X4 = (const float4*)(mode ? (const float*)g_agg : X);
    const uint4* Whi4 = (const uint4*)g_whi[mode];
    const uint4* Wlo4 = (const uint4*)g_wlo[mode];

    for (int kc = 0; kc < 8; kc++) {
        __syncthreads();

        // --- stage A chunk: mask-based tf32 split ---
        #pragma unroll
        for (int j = 0; j < 2; j++) {
            int idx = t + j * 256;
            int row = idx >> 2, c4 = idx & 3;
            int grow = rb + row;
            float4 v = (grow < NN) ? X4[grow * 32 + kc * 4 + c4]
                                   : make_float4(0.f, 0.f, 0.f, 0.f);
            float vv[4] = {v.x, v.y, v.z, v.w};
            int sbase = row * ASTR + c4 * 4;
            #pragma unroll
            for (int i = 0; i < 4; i++) {
                float val = vv[i];
                if (mode) {
                    int c = kc * 16 + c4 * 4 + i;
                    float y = s_bnA[c] * val + s_bnB[c];
                    val = y > 0.f ? y : expm1f(y);
                }
                uint32_t hb = __float_as_uint(val) & TF32_MASK;
                float lof = val - __uint_as_float(hb);     // exact Dekker residual
                sAhi[sbase + i] = hb;
                sAlo[sbase + i] = __float_as_uint(lof) & TF32_MASK;
            }
        }

        // --- stage B chunk: pure copy of preconverted bits ---
        #pragma unroll
        for (int j = 0; j < 2; j++) {
            int idx = t + j * 256;
            int k = idx >> 5, c4 = idx & 31;
            uint4 h = Whi4[(kc * 16 + k) * 32 + c4];
            uint4 l = Wlo4[(kc * 16 + k) * 32 + c4];
            int sbase = k * BSTR + c4 * 4;
            sBhi[sbase + 0] = h.x; sBhi[sbase + 1] = h.y;
            sBhi[sbase + 2] = h.z; sBhi[sbase + 3] = h.w;
            sBlo[sbase + 0] = l.x; sBlo[sbase + 1] = l.y;
            sBlo[sbase + 2] = l.z; sBlo[sbase + 3] = l.w;
        }
        __syncthreads();

        #pragma unroll
        for (int ks = 0; ks < 2; ks++) {
            int kk = ks * 8;
            uint32_t ahi[4], alo[4];
            int ab = (wr + g) * ASTR + kk;
            ahi[0] = sAhi[ab + t4];
            ahi[1] = sAhi[ab + 8 * ASTR + t4];
            ahi[2] = sAhi[ab + t4 + 4];
            ahi[3] = sAhi[ab + 8 * ASTR + t4 + 4];
            alo[0] = sAlo[ab + t4];
            alo[1] = sAlo[ab + 8 * ASTR + t4];
            alo[2] = sAlo[ab + t4 + 4];
            alo[3] = sAlo[ab + 8 * ASTR + t4 + 4];
            #pragma unroll
            for (int nt = 0; nt < 16; nt++) {
                int bcol = nt * 8 + g;
                uint32_t bh0 = sBhi[(kk + t4) * BSTR + bcol];
                uint32_t bh1 = sBhi[(kk + t4 + 4) * BSTR + bcol];
                uint32_t bl0 = sBlo[(kk + t4) * BSTR + bcol];
                uint32_t bl1 = sBlo[(kk + t4 + 4) * BSTR + bcol];
                MMA_TF32(d[nt], ahi, bh0, bh1);
                MMA_TF32(d[nt], ahi, bl0, bl1);
                MMA_TF32(d[nt], alo, bh0, bh1);
            }
        }
    }

    // --- epilogue: store h, attention dots per head, block max of asrc ---
    int r0 = rb + wr + g;
    int r1 = r0 + 8;
    float ds0h0 = 0.f, ds0h1 = 0.f, dd0h0 = 0.f, dd0h1 = 0.f;
    float ds1h0 = 0.f, ds1h1 = 0.f, dd1h0 = 0.f, dd1h1 = 0.f;
    #pragma unroll
    for (int nt = 0; nt < 16; nt++) {
        int c0 = nt * 8 + t4 * 2;
        float a0 = s_atts[c0], a1 = s_atts[c0 + 1];
        float b0 = s_attd[c0], b1 = s_attd[c0 + 1];
        float p0 = d[nt][0] * a0 + d[nt][1] * a1;
        float q0 = d[nt][0] * b0 + d[nt][1] * b1;
        float p1 = d[nt][2] * a0 + d[nt][3] * a1;
        float q1 = d[nt][2] * b0 + d[nt][3] * b1;
        if (nt < 8) { ds0h0 += p0; dd0h0 += q0; ds1h0 += p1; dd1h0 += q1; }
        else        { ds0h1 += p0; dd0h1 += q0; ds1h1 += p1; dd1h1 += q1; }
        if (r0 < NN) *(float2*)&g_h[r0 * FD + c0] = make_float2(d[nt][0], d[nt][1]);
        if (r1 < NN) *(float2*)&g_h[r1 * FD + c0] = make_float2(d[nt][2], d[nt][3]);
    }
    #pragma unroll
    for (int o = 1; o <= 2; o <<= 1) {
        ds0h0 += __shfl_xor_sync(0xFFFFFFFFu, ds0h0, o);
        ds0h1 += __shfl_xor_sync(0xFFFFFFFFu, ds0h1, o);
        dd0h0 += __shfl_xor_sync(0xFFFFFFFFu, dd0h0, o);
        dd0h1 += __shfl_xor_sync(0xFFFFFFFFu, dd0h1, o);
        ds1h0 += __shfl_xor_sync(0xFFFFFFFFu, ds1h0, o);
        ds1h1 += __shfl_xor_sync(0xFFFFFFFFu, ds1h1, o);
        dd1h0 += __shfl_xor_sync(0xFFFFFFFFu, dd1h0, o);
        dd1h1 += __shfl_xor_sync(0xFFFFFFFFu, dd1h1, o);
    }
    if (t4 == 0) {
        if (r0 < NN) {
            g_asrc[r0] = make_float2(ds0h0, ds0h1);
            g_adst[r0] = make_float2(dd0h0, dd0h1);
            atomicMax(&s_m0, encf(ds0h0));
            atomicMax(&s_m1, encf(ds0h1));
        }
        if (r1 < NN) {
            g_asrc[r1] = make_float2(ds1h0, ds1h1);
            g_adst[r1] = make_float2(dd1h0, dd1h1);
            atomicMax(&s_m0, encf(ds1h0));
            atomicMax(&s_m1, encf(ds1h1));
        }
    }
    __syncthreads();
    if (t == 0) {
        atomicMax(&g_gmax[mode][0], s_m0);
        atomicMax(&g_gmax[mode][1], s_m1);
    }
}

// ----- warp-per-dst aggregation: global-max softmax, single gather loop -------
__global__ void k_agg(const float* __restrict__ bias, int slot) {
    __shared__ int   s_src[8][64];
    __shared__ float s_a0[8][64];
    __shared__ float s_a1[8][64];
    int wb   = threadIdx.x >> 5;
    int lane = threadIdx.x & 31;
    int w = (blockIdx.x * blockDim.x + threadIdx.x) >> 5;
    if (w >= NN) return;
    int start = g_offsets[w];
    int deg   = g_offsets[w + 1] - start;

    float2 ad    = g_adst[w];
    float2 aself = g_asrc[w];
    float m0 = lrelu(decf(g_gmax[slot][0]) + ad.x);
    float m1 = lrelu(decf(g_gmax[slot][1]) + ad.y);

    // single pass: gather asrc, exp, stage (first 64 edges), accumulate sums
    float s0 = 0.f, s1 = 0.f;
    #pragma unroll
    for (int it = 0; it < 2; it++) {
        int j = it * 32 + lane;
        bool have = j < deg;
        int sj = 0;
        float x0 = 0.f, x1 = 0.f;
        if (have) {
            sj = g_srt[start + j];
            float2 a = g_asrc[sj];
            x0 = __expf(lrelu(a.x + ad.x) - m0);
            x1 = __expf(lrelu(a.y + ad.y) - m1);
        }
        s_src[wb][it * 32 + lane] = sj;
        s_a0[wb][it * 32 + lane] = x0;
        s_a1[wb][it * 32 + lane] = x1;
        s0 += x0; s1 += x1;
    }
    for (int j = 64 + lane; j < deg; j += 32) {   // astronomically rare tail
        float2 a = g_asrc[g_srt[start + j]];
        s0 += __expf(lrelu(a.x + ad.x) - m0);
        s1 += __expf(lrelu(a.y + ad.y) - m1);
    }
    #pragma unroll
    for (int o = 16; o; o >>= 1) {
        s0 += __shfl_xor_sync(0xFFFFFFFFu, s0, o);
        s1 += __shfl_xor_sync(0xFFFFFFFFu, s1, o);
    }
    float xs0 = __expf(lrelu(aself.x + ad.x) - m0);
    float xs1 = __expf(lrelu(aself.y + ad.y) - m1);
    s0 += xs0; s1 += xs1;
    float inv0 = 1.f / (s0 + 1e-16f);
    float inv1 = 1.f / (s1 + 1e-16f);

    // normalize own staged entries (lane-local), then make visible
    s_a0[wb][lane]      *= inv0;
    s_a0[wb][lane + 32] *= inv0;
    s_a1[wb][lane]      *= inv1;
    s_a1[wb][lane + 32] *= inv1;
    __syncwarp();

    int head = lane >> 4;
    const float4* H4 = (const float4*)g_h;

    float salpha = head ? xs1 * inv1 : xs0 * inv0;
    float4 hv = H4[w * 32 + lane];
    float4 acc = make_float4(salpha * hv.x, salpha * hv.y, salpha * hv.z, salpha * hv.w);
    float4 acc2 = make_float4(0.f, 0.f, 0.f, 0.f);

    const float* sal = head ? s_a1[wb] : s_a0[wb];
    int nd = deg < 64 ? deg : 64;
    int j = 0;
    #pragma unroll 2
    for (; j + 1 < nd; j += 2) {     // dual accumulators -> 2x load MLP
        int sa = s_src[wb][j];
        int sb = s_src[wb][j + 1];
        float aa = sal[j];
        float ab = sal[j + 1];
        float4 va = H4[sa * 32 + lane];
        float4 vb = H4[sb * 32 + lane];
        acc.x  += aa * va.x; acc.y  += aa * va.y;
        acc.z  += aa * va.z; acc.w  += aa * va.w;
        acc2.x += ab * vb.x; acc2.y += ab * vb.y;
        acc2.z += ab * vb.z; acc2.w += ab * vb.w;
    }
    if (j < nd) {
        int sa = s_src[wb][j];
        float aa = sal[j];
        float4 va = H4[sa * 32 + lane];
        acc.x += aa * va.x; acc.y += aa * va.y;
        acc.z += aa * va.z; acc.w += aa * va.w;
    }
    acc.x += acc2.x; acc.y += acc2.y; acc.z += acc2.z; acc.w += acc2.w;

    for (int jj = 64; jj < deg; jj++) {   // rare tail: recompute alpha inline
        int srcj = g_srt[start + jj];
        float2 a = g_asrc[srcj];
        float e = head ? (lrelu(a.y + ad.y) - m1) : (lrelu(a.x + ad.x) - m0);
        float alpha = __expf(e) * (head ? inv1 : inv0);
        float4 v = H4[srcj * 32 + lane];
        acc.x += alpha * v.x;
        acc.y += alpha * v.y;
        acc.z += alpha * v.z;
        acc.w += alpha * v.w;
    }

    float4 b = ((const float4*)bias)[lane];
    acc.x += b.x; acc.y += b.y; acc.z += b.z; acc.w += b.w;
    ((float4*)g_agg)[w * 32 + lane] = acc;
}

// ---------------- batch norm stats + final apply ------------------------------
__global__ void k_bnstats(int slot) {
    int c = threadIdx.x & 127;
    int g = threadIdx.x >> 7;
    float sum = 0.f, sq = 0.f;
    for (int r = blockIdx.x * 2 + g; r < NN; r += gridDim.x * 2) {
        float v = g_agg[r * FD + c];
        sum += v;
        sq = fmaf(v, v, sq);
    }
    atomicAdd(&g_bnsum[slot][c], (double)sum);
    atomicAdd(&g_bnsq[slot][c],  (double)sq);
}

__global__ void k_bnapply(const float* __restrict__ gamma,
                          const float* __restrict__ beta,
                          float* __restrict__ out) {
    int i = blockIdx.x * blockDim.x + threadIdx.x;
    if (i >= NN * 32) return;
    int c4 = (i & 31) * 4;
    float4 v  = ((const float4*)g_agg)[i];
    float4 gm = ((const float4*)gamma)[i & 31];
    float4 bt = ((const float4*)beta)[i & 31];
    float res[4];
    float vin[4] = {v.x, v.y, v.z, v.w};
    float gs[4]  = {gm.x, gm.y, gm.z, gm.w};
    float bs[4]  = {bt.x, bt.y, bt.z, bt.w};
    #pragma unroll
    for (int k = 0; k < 4; k++) {
        int c = c4 + k;
        float mean = (float)(g_bnsum[1][c] / (double)NN);
        float var  = (float)(g_bnsq[1][c] / (double)NN) - mean * mean;
        float is   = rsqrtf(var + BN_EPS);
        float y = (vin[k] - mean) * is * gs[k] + bs[k];
        res[k] = y > 0.f ? y : expm1f(y);
    }
    ((float4*)out)[i] = make_float4(res[0], res[1], res[2], res[3]);
}

// ---------------- launch: kernel launches ONLY (graph-capture safe) -----------
extern "C" void kernel_launch(void* const* d_in, const int* in_sizes, int n_in,
                              void* d_out, int out_size) {
    const float* x        = (const float*)d_in[0];
    const int*   eidx     = (const int*)d_in[1];
    const float* W1       = (const float*)d_in[2];
    const float* att_src1 = (const float*)d_in[3];
    const float* att_dst1 = (const float*)d_in[4];
    const float* b1       = (const float*)d_in[5];
    const float* W2       = (const float*)d_in[6];
    const float* att_src2 = (const float*)d_in[7];
    const float* att_dst2 = (const float*)d_in[8];
    const float* b2       = (const float*)d_in[9];
    const float* g1       = (const float*)d_in[10];
    const float* be1      = (const float*)d_in[11];
    const float* g2       = (const float*)d_in[12];
    const float* be2      = (const float*)d_in[13];
    float* out = (float*)d_out;

    const int* esrc = eidx;
    const int* edst = eidx + EE;

    const int WARP_BLOCKS = NN / 8;                 // 6250
    const int MMA_BLOCKS  = (NN + 127) / 128;       // 391
    const int E4_BLOCKS   = (EE / 4 + 255) / 256;

    k_prep<<<(NN + 255) / 256, 256>>>(W1, W2);
    k_hist<<<E4_BLOCKS, 256>>>(edst);
    k_scan<<<1, 1024>>>();
    k_scatter<<<E4_BLOCKS, 256>>>(esrc, edst);

    // --- layer 1 ---
    k_gemm_mma<<<MMA_BLOCKS, 256>>>(x, g1, be1, att_src1, att_dst1, 0);
    k_agg<<<WARP_BLOCKS, 256>>>(b1, 0);
    k_bnstats<<<256, 256>>>(0);

    // --- layer 2 (BN+ELU of layer 1 fused into A-load) ---
    k_gemm_mma<<<MMA_BLOCKS, 256>>>(x, g2, be2, att_src2, att_dst2, 1);
    k_agg<<<WARP_BLOCKS, 256>>>(b2, 1);
    k_bnstats<<<256, 256>>>(1);
    k_bnapply<<<WARP_BLOCKS, 256>>>(g2, be2, out);
}

// round 12
// speedup vs baseline: 1.0438x; 1.0001x over previous
#include <cuda_runtime.h>
#include <cuda_bf16.h>
#include <cstdint>

#define NN 50000
#define EE 800000
#define FD 128           // hidden = heads*C = 2*64
#define NEG 0.2f
#define BN_EPS 1e-5f

// ---------------- scratch (device globals; referenced ONLY inside kernels) ----
__device__ __align__(16) float  g_h[NN * FD];    // per-layer features (GEMM out)
__device__ __align__(16) float  g_agg[NN * FD];  // GAT aggregate output (pre-BN)
__device__ __align__(16) uint32_t g_whi[2][FD * FD];  // W tf32-hi bits per layer
__device__ __align__(16) uint32_t g_wlo[2][FD * FD];  // W tf32-lo bits per layer
__device__ float2 g_asrc[NN];
__device__ float2 g_adst[NN];
__device__ int    g_counts[NN];
__device__ int    g_cursor[NN];
__device__ int    g_offsets[NN + 1];
__device__ int    g_srt[EE];
__device__ double g_bnsum[2][FD];
__device__ double g_bnsq[2][FD];
__device__ unsigned int g_gmax[2][2];   // [layer][head]: encoded global max of asrc

__device__ __forceinline__ int clampN(int v) {
    return v < 0 ? 0 : (v >= NN ? NN - 1 : v);
}
__device__ __forceinline__ float lrelu(float v) { return v > 0.f ? v : NEG * v; }

// monotone float<->uint encoding for atomicMax
__device__ __forceinline__ unsigned int encf(float f) {
    unsigned int u = __float_as_uint(f);
    return (u & 0x80000000u) ? ~u : (u | 0x80000000u);
}
__device__ __forceinline__ float decf(unsigned int u) {
    return __uint_as_float((u & 0x80000000u) ? (u ^ 0x80000000u) : ~u);
}

__device__ __forceinline__ uint32_t f2tf32(float f) {
    uint32_t r;
    asm("cvt.rna.tf32.f32 %0, %1;" : "=r"(r) : "f"(f));
    return r;
}

#define MMA_TF32(d, a, b0, b1) \
    asm volatile("mma.sync.aligned.m16n8k8.row.col.f32.tf32.tf32.f32 " \
        "{%0,%1,%2,%3}, {%4,%5,%6,%7}, {%8,%9}, {%0,%1,%2,%3};" \
        : "+f"((d)[0]), "+f"((d)[1]), "+f"((d)[2]), "+f"((d)[3]) \
        : "r"((a)[0]), "r"((a)[1]), "r"((a)[2]), "r"((a)[3]), \
          "r"(b0), "r"(b1))

// -------- prep: zero counters/stats + precompute W tf32 hi/lo (both layers) ---
__global__ void k_prep(const float* __restrict__ W1, const float* __restrict__ W2) {
    int i = blockIdx.x * blockDim.x + threadIdx.x;
    if (i < NN) g_counts[i] = 0;
    if (i < FD) {
        g_bnsum[0][i] = 0.0; g_bnsq[0][i] = 0.0;
        g_bnsum[1][i] = 0.0; g_bnsq[1][i] = 0.0;
    }
    if (i < 4) g_gmax[i >> 1][i & 1] = 0u;
    if (i < FD * FD) {
        #pragma unroll
        for (int l = 0; l < 2; l++) {
            float w = (l ? W2 : W1)[i];
            uint32_t hb = f2tf32(w);
            float lof = w - __uint_as_float(hb);
            g_whi[l][i] = hb;
            g_wlo[l][i] = f2tf32(lof);
        }
    }
}

// ---------------- counting sort by destination --------------------------------
__global__ void k_hist(const int* __restrict__ dst) {
    int e4 = blockIdx.x * blockDim.x + threadIdx.x;
    if (e4 < EE / 4) {
        int4 d = ((const int4*)dst)[e4];
        atomicAdd(&g_counts[clampN(d.x)], 1);
        atomicAdd(&g_counts[clampN(d.y)], 1);
        atomicAdd(&g_counts[clampN(d.z)], 1);
        atomicAdd(&g_counts[clampN(d.w)], 1);
    }
}

__global__ void k_scan() {
    __shared__ int ssum[1024];
    const int CH = (NN + 1023) / 1024;
    int t = threadIdx.x;
    int base = t * CH;
    int s = 0;
    for (int i = 0; i < CH; i++) {
        int idx = base + i;
        if (idx < NN) s += g_counts[idx];
    }
    ssum[t] = s;
    __syncthreads();
    for (int o = 1; o < 1024; o <<= 1) {
        int u = (t >= o) ? ssum[t - o] : 0;
        __syncthreads();
        ssum[t] += u;
        __syncthreads();
    }
    int off = ssum[t] - s;
    for (int i = 0; i < CH; i++) {
        int idx = base + i;
        if (idx < NN) {
            g_offsets[idx] = off;
            g_cursor[idx]  = off;
            off += g_counts[idx];
        }
    }
    if (t == 0) g_offsets[NN] = EE;
}

__global__ void k_scatter(const int* __restrict__ src,
                          const int* __restrict__ dst) {
    int e4 = blockIdx.x * blockDim.x + threadIdx.x;
    if (e4 < EE / 4) {
        int4 d = ((const int4*)dst)[e4];
        int4 s = ((const int4*)src)[e4];
        int p;
        p = atomicAdd(&g_cursor[clampN(d.x)], 1); if (p >= 0 && p < EE) g_srt[p] = clampN(s.x);
        p = atomicAdd(&g_cursor[clampN(d.y)], 1); if (p >= 0 && p < EE) g_srt[p] = clampN(s.y);
        p = atomicAdd(&g_cursor[clampN(d.z)], 1); if (p >= 0 && p < EE) g_srt[p] = clampN(s.z);
        p = atomicAdd(&g_cursor[clampN(d.w)], 1); if (p >= 0 && p < EE) g_srt[p] = clampN(s.w);
    }
}

// ============== 3xTF32 mma.sync GEMM + attention-score epilogue ==============
// A hi-split via mantissa mask (LOP3+FADD+LOP3, no cvt); B preconverted in k_prep.
#define ASTR 20    // A row stride (conflict-free fragment access)
#define BSTR 136   // B k-row stride; 136 % 32 == 8 -> conflict-free
#define TF32_MASK 0xFFFFE000u

__global__ void k_gemm_mma(const float* __restrict__ X,
                           const float* __restrict__ gamma, const float* __restrict__ beta,
                           const float* __restrict__ att_s, const float* __restrict__ att_d,
                           int mode) {
    __shared__ uint32_t sAhi[128 * ASTR];
    __shared__ uint32_t sAlo[128 * ASTR];
    __shared__ uint32_t sBhi[16 * BSTR];
    __shared__ uint32_t sBlo[16 * BSTR];
    __shared__ float s_atts[FD], s_attd[FD], s_bnA[FD], s_bnB[FD];
    __shared__ unsigned int s_m0, s_m1;

    int t = threadIdx.x;
    int rb = blockIdx.x * 128;

    if (t == 0) { s_m0 = 0u; s_m1 = 0u; }
    if (t < FD) {
        s_atts[t] = att_s[t];
        s_attd[t] = att_d[t];
        if (mode) {
            double mean = g_bnsum[0][t] / (double)NN;
            double var  = g_bnsq[0][t] / (double)NN - mean * mean;
            float a = gamma[t] * rsqrtf((float)var + BN_EPS);
            s_bnA[t] = a;
            s_bnB[t] = beta[t] - (float)mean * a;
        }
    }

    int lane = t & 31, warp = t >> 5;
    int g  = lane >> 2;       // groupID (row within fragment)
    int t4 = lane & 3;        // threadID in group
    int wr = warp * 16;       // warp row base within tile

    float d[16][4];
    #pragma unroll
    for (int nt = 0; nt < 16; nt++) {
        d[nt][0] = 0.f; d[nt][1] = 0.f; d[nt][2] = 0.f; d[nt][3] = 0.f;
    }

    const float4* X4 = (const float4*)(mode ? (const float*)g_agg : X);
    const uint4* Whi4 = (const uint4*)g_whi[mode];
    const uint4* Wlo4 = (const uint4*)g_wlo[mode];

    for (int kc = 0; kc < 8; kc++) {
        __syncthreads();

        // --- stage A chunk: mask-based tf32 split ---
        #pragma unroll
        for (int j = 0; j < 2; j++) {
            int idx = t + j * 256;
            int row = idx >> 2, c4 = idx & 3;
            int grow = rb + row;
            float4 v = (grow < NN) ? X4[grow * 32 + kc * 4 + c4]
                                   : make_float4(0.f, 0.f, 0.f, 0.f);
            float vv[4] = {v.x, v.y, v.z, v.w};
            int sbase = row * ASTR + c4 * 4;
            #pragma unroll
            for (int i = 0; i < 4; i++) {
                float val = vv[i];
                if (mode) {
                    int c = kc * 16 + c4 * 4 + i;
                    float y = s_bnA[c] * val + s_bnB[c];
                    val = y > 0.f ? y : expm1f(y);
                }
                uint32_t hb = __float_as_uint(val) & TF32_MASK;
                float lof = val - __uint_as_float(hb);     // exact Dekker residual
                sAhi[sbase + i] = hb;
                sAlo[sbase + i] = __float_as_uint(lof) & TF32_MASK;
            }
        }

        // --- stage B chunk: pure copy of preconverted bits ---
        #pragma unroll
        for (int j = 0; j < 2; j++) {
            int idx = t + j * 256;
            int k = idx >> 5, c4 = idx & 31;
            uint4 h = Whi4[(kc * 16 + k) * 32 + c4];
            uint4 l = Wlo4[(kc * 16 + k) * 32 + c4];
            int sbase = k * BSTR + c4 * 4;
            sBhi[sbase + 0] = h.x; sBhi[sbase + 1] = h.y;
            sBhi[sbase + 2] = h.z; sBhi[sbase + 3] = h.w;
            sBlo[sbase + 0] = l.x; sBlo[sbase + 1] = l.y;
            sBlo[sbase + 2] = l.z; sBlo[sbase + 3] = l.w;
        }
        __syncthreads();

        #pragma unroll
        for (int ks = 0; ks < 2; ks++) {
            int kk = ks * 8;
            uint32_t ahi[4], alo[4];
            int ab = (wr + g) * ASTR + kk;
            ahi[0] = sAhi[ab + t4];
            ahi[1] = sAhi[ab + 8 * ASTR + t4];
            ahi[2] = sAhi[ab + t4 + 4];
            ahi[3] = sAhi[ab + 8 * ASTR + t4 + 4];
            alo[0] = sAlo[ab + t4];
            alo[1] = sAlo[ab + 8 * ASTR + t4];
            alo[2] = sAlo[ab + t4 + 4];
            alo[3] = sAlo[ab + 8 * ASTR + t4 + 4];
            #pragma unroll
            for (int nt = 0; nt < 16; nt++) {
                int bcol = nt * 8 + g;
                uint32_t bh0 = sBhi[(kk + t4) * BSTR + bcol];
                uint32_t bh1 = sBhi[(kk + t4 + 4) * BSTR + bcol];
                uint32_t bl0 = sBlo[(kk + t4) * BSTR + bcol];
                uint32_t bl1 = sBlo[(kk + t4 + 4) * BSTR + bcol];
                MMA_TF32(d[nt], ahi, bh0, bh1);
                MMA_TF32(d[nt], ahi, bl0, bl1);
                MMA_TF32(d[nt], alo, bh0, bh1);
            }
        }
    }

    // --- epilogue: store h, attention dots per head, block max of asrc ---
    int r0 = rb + wr + g;
    int r1 = r0 + 8;
    float ds0h0 = 0.f, ds0h1 = 0.f, dd0h0 = 0.f, dd0h1 = 0.f;
    float ds1h0 = 0.f, ds1h1 = 0.f, dd1h0 = 0.f, dd1h1 = 0.f;
    #pragma unroll
    for (int nt = 0; nt < 16; nt++) {
        int c0 = nt * 8 + t4 * 2;
        float a0 = s_atts[c0], a1 = s_atts[c0 + 1];
        float b0 = s_attd[c0], b1 = s_attd[c0 + 1];
        float p0 = d[nt][0] * a0 + d[nt][1] * a1;
        float q0 = d[nt][0] * b0 + d[nt][1] * b1;
        float p1 = d[nt][2] * a0 + d[nt][3] * a1;
        float q1 = d[nt][2] * b0 + d[nt][3] * b1;
        if (nt < 8) { ds0h0 += p0; dd0h0 += q0; ds1h0 += p1; dd1h0 += q1; }
        else        { ds0h1 += p0; dd0h1 += q0; ds1h1 += p1; dd1h1 += q1; }
        if (r0 < NN) *(float2*)&g_h[r0 * FD + c0] = make_float2(d[nt][0], d[nt][1]);
        if (r1 < NN) *(float2*)&g_h[r1 * FD + c0] = make_float2(d[nt][2], d[nt][3]);
    }
    #pragma unroll
    for (int o = 1; o <= 2; o <<= 1) {
        ds0h0 += __shfl_xor_sync(0xFFFFFFFFu, ds0h0, o);
        ds0h1 += __shfl_xor_sync(0xFFFFFFFFu, ds0h1, o);
        dd0h0 += __shfl_xor_sync(0xFFFFFFFFu, dd0h0, o);
        dd0h1 += __shfl_xor_sync(0xFFFFFFFFu, dd0h1, o);
        ds1h0 += __shfl_xor_sync(0xFFFFFFFFu, ds1h0, o);
        ds1h1 += __shfl_xor_sync(0xFFFFFFFFu, ds1h1, o);
        dd1h0 += __shfl_xor_sync(0xFFFFFFFFu, dd1h0, o);
        dd1h1 += __shfl_xor_sync(0xFFFFFFFFu, dd1h1, o);
    }
    if (t4 == 0) {
        if (r0 < NN) {
            g_asrc[r0] = make_float2(ds0h0, ds0h1);
            g_adst[r0] = make_float2(dd0h0, dd0h1);
            atomicMax(&s_m0, encf(ds0h0));
            atomicMax(&s_m1, encf(ds0h1));
        }
        if (r1 < NN) {
            g_asrc[r1] = make_float2(ds1h0, ds1h1);
            g_adst[r1] = make_float2(dd1h0, dd1h1);
            atomicMax(&s_m0, encf(ds1h0));
            atomicMax(&s_m1, encf(ds1h1));
        }
    }
    __syncthreads();
    if (t == 0) {
        atomicMax(&g_gmax[mode][0], s_m0);
        atomicMax(&g_gmax[mode][1], s_m1);
    }
}

// ----- warp-per-dst aggregation: global-max softmax, single gather loop -------
__global__ void k_agg(const float* __restrict__ bias, int slot) {
    __shared__ int   s_src[8][64];
    __shared__ float s_a0[8][64];
    __shared__ float s_a1[8][64];
    int wb   = threadIdx.x >> 5;
    int lane = threadIdx.x & 31;
    int w = (blockIdx.x * blockDim.x + threadIdx.x) >> 5;
    if (w >= NN) return;
    int start = g_offsets[w];
    int deg   = g_offsets[w + 1] - start;

    float2 ad    = g_adst[w];
    float2 aself = g_asrc[w];
    float m0 = lrelu(decf(g_gmax[slot][0]) + ad.x);
    float m1 = lrelu(decf(g_gmax[slot][1]) + ad.y);

    // single pass: gather asrc, exp, stage (first 64 edges), accumulate sums
    float s0 = 0.f, s1 = 0.f;
    #pragma unroll
    for (int it = 0; it < 2; it++) {
        int j = it * 32 + lane;
        bool have = j < deg;
        int sj = 0;
        float x0 = 0.f, x1 = 0.f;
        if (have) {
            sj = g_srt[start + j];
            float2 a = g_asrc[sj];
            x0 = __expf(lrelu(a.x + ad.x) - m0);
            x1 = __expf(lrelu(a.y + ad.y) - m1);
        }
        s_src[wb][it * 32 + lane] = sj;
        s_a0[wb][it * 32 + lane] = x0;
        s_a1[wb][it * 32 + lane] = x1;
        s0 += x0; s1 += x1;
    }
    for (int j = 64 + lane; j < deg; j += 32) {   // astronomically rare tail
        float2 a = g_asrc[g_srt[start + j]];
        s0 += __expf(lrelu(a.x + ad.x) - m0);
        s1 += __expf(lrelu(a.y + ad.y) - m1);
    }
    #pragma unroll
    for (int o = 16; o; o >>= 1) {
        s0 += __shfl_xor_sync(0xFFFFFFFFu, s0, o);
        s1 += __shfl_xor_sync(0xFFFFFFFFu, s1, o);
    }
    float xs0 = __expf(lrelu(aself.x + ad.x) - m0);
    float xs1 = __expf(lrelu(aself.y + ad.y) - m1);
    s0 += xs0; s1 += xs1;
    float inv0 = 1.f / (s0 + 1e-16f);
    float inv1 = 1.f / (s1 + 1e-16f);

    // normalize own staged entries (lane-local), then make visible
    s_a0[wb][lane]      *= inv0;
    s_a0[wb][lane + 32] *= inv0;
    s_a1[wb][lane]      *= inv1;
    s_a1[wb][lane + 32] *= inv1;
    __syncwarp();

    int head = lane >> 4;
    const float4* H4 = (const float4*)g_h;

    float salpha = head ? xs1 * inv1 : xs0 * inv0;
    float4 hv = H4[w * 32 + lane];
    float4 acc = make_float4(salpha * hv.x, salpha * hv.y, salpha * hv.z, salpha * hv.w);
    float4 acc2 = make_float4(0.f, 0.f, 0.f, 0.f);

    const float* sal = head ? s_a1[wb] : s_a0[wb];
    int nd = deg < 64 ? deg : 64;
    int j = 0;
    #pragma unroll 2
    for (; j + 1 < nd; j += 2) {     // dual accumulators -> 2x load MLP
        int sa = s_src[wb][j];
        int sb = s_src[wb][j + 1];
        float aa = sal[j];
        float ab = sal[j + 1];
        float4 va = H4[sa * 32 + lane];
        float4 vb = H4[sb * 32 + lane];
        acc.x  += aa * va.x; acc.y  += aa * va.y;
        acc.z  += aa * va.z; acc.w  += aa * va.w;
        acc2.x += ab * vb.x; acc2.y += ab * vb.y;
        acc2.z += ab * vb.z; acc2.w += ab * vb.w;
    }
    if (j < nd) {
        int sa = s_src[wb][j];
        float aa = sal[j];
        float4 va = H4[sa * 32 + lane];
        acc.x += aa * va.x; acc.y += aa * va.y;
        acc.z += aa * va.z; acc.w += aa * va.w;
    }
    acc.x += acc2.x; acc.y += acc2.y; acc.z += acc2.z; acc.w += acc2.w;

    for (int jj = 64; jj < deg; jj++) {   // rare tail: recompute alpha inline
        int srcj = g_srt[start + jj];
        float2 a = g_asrc[srcj];
        float e = head ? (lrelu(a.y + ad.y) - m1) : (lrelu(a.x + ad.x) - m0);
        float alpha = __expf(e) * (head ? inv1 : inv0);
        float4 v = H4[srcj * 32 + lane];
        acc.x += alpha * v.x;
        acc.y += alpha * v.y;
        acc.z += alpha * v.z;
        acc.w += alpha * v.w;
    }

    float4 b = ((const float4*)bias)[lane];
    acc.x += b.x; acc.y += b.y; acc.z += b.z; acc.w += b.w;
    ((float4*)g_agg)[w * 32 + lane] = acc;
}

// ---------------- batch norm stats + final apply ------------------------------
__global__ void k_bnstats(int slot) {
    int c = threadIdx.x & 127;
    int g = threadIdx.x >> 7;
    float sum = 0.f, sq = 0.f;
    for (int r = blockIdx.x * 2 + g; r < NN; r += gridDim.x * 2) {
        float v = g_agg[r * FD + c];
        sum += v;
        sq = fmaf(v, v, sq);
    }
    atomicAdd(&g_bnsum[slot][c], (double)sum);
    atomicAdd(&g_bnsq[slot][c],  (double)sq);
}

__global__ void k_bnapply(const float* __restrict__ gamma,
                          const float* __restrict__ beta,
                          float* __restrict__ out) {
    int i = blockIdx.x * blockDim.x + threadIdx.x;
    if (i >= NN * 32) return;
    int c4 = (i & 31) * 4;
    float4 v  = ((const float4*)g_agg)[i];
    float4 gm = ((const float4*)gamma)[i & 31];
    float4 bt = ((const float4*)beta)[i & 31];
    float res[4];
    float vin[4] = {v.x, v.y, v.z, v.w};
    float gs[4]  = {gm.x, gm.y, gm.z, gm.w};
    float bs[4]  = {bt.x, bt.y, bt.z, bt.w};
    #pragma unroll
    for (int k = 0; k < 4; k++) {
        int c = c4 + k;
        float mean = (float)(g_bnsum[1][c] / (double)NN);
        float var  = (float)(g_bnsq[1][c] / (double)NN) - mean * mean;
        float is   = rsqrtf(var + BN_EPS);
        float y = (vin[k] - mean) * is * gs[k] + bs[k];
        res[k] = y > 0.f ? y : expm1f(y);
    }
    ((float4*)out)[i] = make_float4(res[0], res[1], res[2], res[3]);
}

// ---------------- launch: kernel launches ONLY (graph-capture safe) -----------
extern "C" void kernel_launch(void* const* d_in, const int* in_sizes, int n_in,
                              void* d_out, int out_size) {
    const float* x        = (const float*)d_in[0];
    const int*   eidx     = (const int*)d_in[1];
    const float* W1       = (const float*)d_in[2];
    const float* att_src1 = (const float*)d_in[3];
    const float* att_dst1 = (const float*)d_in[4];
    const float* b1       = (const float*)d_in[5];
    const float* W2       = (const float*)d_in[6];
    const float* att_src2 = (const float*)d_in[7];
    const float* att_dst2 = (const float*)d_in[8];
    const float* b2       = (const float*)d_in[9];
    const float* g1       = (const float*)d_in[10];
    const float* be1      = (const float*)d_in[11];
    const float* g2       = (const float*)d_in[12];
    const float* be2      = (const float*)d_in[13];
    float* out = (float*)d_out;

    const int* esrc = eidx;
    const int* edst = eidx + EE;

    const int WARP_BLOCKS = NN / 8;                 // 6250
    const int MMA_BLOCKS  = (NN + 127) / 128;       // 391
    const int E4_BLOCKS   = (EE / 4 + 255) / 256;

    k_prep<<<(NN + 255) / 256, 256>>>(W1, W2);
    k_hist<<<E4_BLOCKS, 256>>>(edst);
    k_scan<<<1, 1024>>>();
    k_scatter<<<E4_BLOCKS, 256>>>(esrc, edst);

    // --- layer 1 ---
    k_gemm_mma<<<MMA_BLOCKS, 256>>>(x, g1, be1, att_src1, att_dst1, 0);
    k_agg<<<WARP_BLOCKS, 256>>>(b1, 0);
    k_bnstats<<<256, 256>>>(0);

    // --- layer 2 (BN+ELU of layer 1 fused into A-load) ---
    k_gemm_mma<<<MMA_BLOCKS, 256>>>(x, g2, be2, att_src2, att_dst2, 1);
    k_agg<<<WARP_BLOCKS, 256>>>(b2, 1);
    k_bnstats<<<256, 256>>>(1);
    k_bnapply<<<WARP_BLOCKS, 256>>>(g2, be2, out);
}